// round 1
// baseline (speedup 1.0000x reference)
#include <cuda_runtime.h>
#include <cstdint>

// ---------------------------------------------------------------------------
// Problem constants (fixed by the reference)
// ---------------------------------------------------------------------------
#define NMI 100000
#define NDI 50000
#define HMAX 256

// ---------------------------------------------------------------------------
// Scratch: __device__ globals (no allocation allowed)
// ---------------------------------------------------------------------------
__device__ float g_hmi_a[(size_t)NMI * HMAX];
__device__ float g_hmi_b[(size_t)NMI * HMAX];
__device__ float g_hdi_a[(size_t)NDI * HMAX];
__device__ float g_hdi_b[(size_t)NDI * HMAX];
__device__ float g_agg_mi[(size_t)NMI * HMAX];
__device__ float g_agg_di[(size_t)NDI * HMAX];
__device__ float g_deg_mi[NMI];
__device__ float g_deg_di[NDI];

static inline int cdiv(int a, int b) { return (a + b - 1) / b; }

// ---------------------------------------------------------------------------
// Degree count (float so the GEMM rowscale path can read it directly)
// ---------------------------------------------------------------------------
__global__ void deg_kernel(const int* __restrict__ src, const int* __restrict__ dst,
                           int E, float* __restrict__ deg_mi, float* __restrict__ deg_di)
{
    int i = blockIdx.x * blockDim.x + threadIdx.x;
    if (i < E) {
        atomicAdd(&deg_mi[src[i]], 1.0f);
        atomicAdd(&deg_di[dst[i]], 1.0f);
    }
}

// ---------------------------------------------------------------------------
// Vectorized global reduction (sm_90+): 4 floats per op
// ---------------------------------------------------------------------------
__device__ __forceinline__ void red_add_v4(float* p, float4 v)
{
    asm volatile("red.global.add.v4.f32 [%0], {%1, %2, %3, %4};"
                 :: "l"(p), "f"(v.x), "f"(v.y), "f"(v.z), "f"(v.w)
                 : "memory");
}

// ---------------------------------------------------------------------------
// Fused bidirectional scatter: one warp per edge.
//   agg_di[dst] += h_mi[src]   (C floats)
//   agg_mi[src] += h_di[dst]   (C floats)
// ---------------------------------------------------------------------------
__global__ void scatter_kernel(const float* __restrict__ hmi, const float* __restrict__ hdi,
                               const int* __restrict__ src, const int* __restrict__ dst,
                               int E, int C,
                               float* __restrict__ agg_di, float* __restrict__ agg_mi)
{
    int gw = (blockIdx.x * blockDim.x + threadIdx.x) >> 5;
    int lane = threadIdx.x & 31;
    if (gw >= E) return;
    int s = src[gw];
    int d = dst[gw];
    const float4* rs = (const float4*)(hmi + (size_t)s * C);
    const float4* rd = (const float4*)(hdi + (size_t)d * C);
    float*        ad = agg_di + (size_t)d * C;
    float*        am = agg_mi + (size_t)s * C;
    int n4 = C >> 2;
    for (int j = lane; j < n4; j += 32) {
        float4 a = rs[j];
        float4 b = rd[j];
        red_add_v4(ad + j * 4, a);
        red_add_v4(am + j * 4, b);
    }
}

// ---------------------------------------------------------------------------
// Fused dual-operand SGEMM:
//   D[n,c] = sum_k scale(n)*A1[n,k]*W1[c,k]  (+ sum_k A2[n,k]*W2[c,k])
//            + bias[c] (+ addend[n,c]) ; optional relu
// scale(n) = 1/max(deg[n],1) when deg != nullptr.
// A row-major [N,K], W row-major [Co,K]. BM=BN=128, BK=8, 256 thr, 8x8 micro.
// ---------------------------------------------------------------------------
#define BM 128
#define BN 128
#define BKK 8
#define TM 8
#define TN 8

__global__ __launch_bounds__(256, 2)
void gemm_dual(const float* __restrict__ A1, const float* __restrict__ deg,
               const float* __restrict__ W1,
               const float* __restrict__ A2, const float* __restrict__ W2,
               const float* __restrict__ bias, const float* __restrict__ addend,
               float* __restrict__ D, int N, int K, int Co, int relu)
{
    __shared__ float As[BKK][BM];
    __shared__ float Bs[BKK][BN];

    const int tid  = threadIdx.x;
    const int row0 = blockIdx.x * BM;
    const int col0 = blockIdx.y * BN;

    const int ty = tid >> 4;          // 0..15
    const int tx = tid & 15;          // 0..15

    const int lr = tid >> 1;          // 0..127 loader row
    const int lk = (tid & 1) << 2;    // 0 or 4

    float acc[TM][TN];
#pragma unroll
    for (int i = 0; i < TM; i++)
#pragma unroll
        for (int j = 0; j < TN; j++) acc[i][j] = 0.0f;

    const int  a_row = row0 + lr;
    const int  b_col = col0 + lr;
    float rscale = 1.0f;
    if (deg != nullptr && a_row < N) rscale = 1.0f / fmaxf(deg[a_row], 1.0f);

    const int KT = (A2 != nullptr) ? (2 * K) : K;

    for (int k0 = 0; k0 < KT; k0 += BKK) {
        // ---- A tile ----
        float4 av = make_float4(0.f, 0.f, 0.f, 0.f);
        if (a_row < N) {
            int kg = k0 + lk;
            if (kg < K) {
                av = *(const float4*)(A1 + (size_t)a_row * K + kg);
                av.x *= rscale; av.y *= rscale; av.z *= rscale; av.w *= rscale;
            } else {
                av = *(const float4*)(A2 + (size_t)a_row * K + (kg - K));
            }
        }
        As[lk + 0][lr] = av.x;
        As[lk + 1][lr] = av.y;
        As[lk + 2][lr] = av.z;
        As[lk + 3][lr] = av.w;

        // ---- B (weight) tile ----
        float4 bv = make_float4(0.f, 0.f, 0.f, 0.f);
        if (b_col < Co) {
            int kg = k0 + lk;
            const float* W = (kg < K) ? W1 : W2;
            int kk = (kg < K) ? kg : (kg - K);
            bv = *(const float4*)(W + (size_t)b_col * K + kk);
        }
        Bs[lk + 0][lr] = bv.x;
        Bs[lk + 1][lr] = bv.y;
        Bs[lk + 2][lr] = bv.z;
        Bs[lk + 3][lr] = bv.w;

        __syncthreads();

#pragma unroll
        for (int kk = 0; kk < BKK; kk++) {
            float ar[TM], br[TN];
            *(float4*)&ar[0] = *(const float4*)&As[kk][ty * TM];
            *(float4*)&ar[4] = *(const float4*)&As[kk][ty * TM + 4];
            *(float4*)&br[0] = *(const float4*)&Bs[kk][tx * TN];
            *(float4*)&br[4] = *(const float4*)&Bs[kk][tx * TN + 4];
#pragma unroll
            for (int i = 0; i < TM; i++)
#pragma unroll
                for (int j = 0; j < TN; j++)
                    acc[i][j] = fmaf(ar[i], br[j], acc[i][j]);
        }
        __syncthreads();
    }

    // ---- epilogue ----
#pragma unroll
    for (int i = 0; i < TM; i++) {
        int r = row0 + ty * TM + i;
        if (r >= N) continue;
#pragma unroll
        for (int j = 0; j < TN; j++) {
            int c = col0 + tx * TN + j;
            if (c >= Co) continue;
            float v = acc[i][j];
            if (bias)   v += bias[c];
            if (addend) v += addend[(size_t)r * Co + c];
            if (relu)   v = fmaxf(v, 0.0f);
            D[(size_t)r * Co + c] = v;
        }
    }
}

// ---------------------------------------------------------------------------
// Classifier: out[l] = dot(h_mi[lsrc[l]], h_di[ldst[l]]) over 64 dims.
// 16 threads per label, float4 loads, shfl reduce within 16-lane groups.
// ---------------------------------------------------------------------------
__global__ void dot_kernel(const float* __restrict__ hmi, const float* __restrict__ hdi,
                           const int* __restrict__ lsrc, const int* __restrict__ ldst,
                           int L, float* __restrict__ out)
{
    int idx = blockIdx.x * blockDim.x + threadIdx.x;
    int lab = idx >> 4;
    int ln  = idx & 15;
    if (lab >= L) return;
    int s = lsrc[lab];
    int d = ldst[lab];
    float4 a = *(const float4*)(hmi + (size_t)s * 64 + ln * 4);
    float4 b = *(const float4*)(hdi + (size_t)d * 64 + ln * 4);
    float v = a.x * b.x + a.y * b.y + a.z * b.z + a.w * b.w;
    v += __shfl_down_sync(0xFFFFFFFFu, v, 8, 16);
    v += __shfl_down_sync(0xFFFFFFFFu, v, 4, 16);
    v += __shfl_down_sync(0xFFFFFFFFu, v, 2, 16);
    v += __shfl_down_sync(0xFFFFFFFFu, v, 1, 16);
    if (ln == 0) out[lab] = v;
}

// ---------------------------------------------------------------------------
// Launch
// ---------------------------------------------------------------------------
extern "C" void kernel_launch(void* const* d_in, const int* in_sizes, int n_in,
                              void* d_out, int out_size)
{
    const float* x_mi   = (const float*)d_in[0];
    const float* x_di   = (const float*)d_in[1];
    const float* W_mi   = (const float*)d_in[2];
    const float* b_mi   = (const float*)d_in[3];
    const float* W_di   = (const float*)d_in[4];
    const float* b_di   = (const float*)d_in[5];
    const float* emb_mi = (const float*)d_in[6];
    const float* emb_di = (const float*)d_in[7];

    const float *Wl[3][2], *bl[3][2], *Wr[3][2];  // [layer][0=md,1=dm]
    int idx = 8;
    for (int l = 0; l < 3; l++)
        for (int r = 0; r < 2; r++) {
            Wl[l][r] = (const float*)d_in[idx++];
            bl[l][r] = (const float*)d_in[idx++];
            Wr[l][r] = (const float*)d_in[idx++];
        }
    const int* edge_src  = (const int*)d_in[26];
    const int* edge_dst  = (const int*)d_in[27];
    const int* label_src = (const int*)d_in[28];
    const int* label_dst = (const int*)d_in[29];
    const int E = in_sizes[26];
    const int L = in_sizes[28];
    float* out = (float*)d_out;

    float *hmi[2], *hdi[2], *agg_mi, *agg_di, *deg_mi, *deg_di;
    cudaGetSymbolAddress((void**)&hmi[0], g_hmi_a);
    cudaGetSymbolAddress((void**)&hmi[1], g_hmi_b);
    cudaGetSymbolAddress((void**)&hdi[0], g_hdi_a);
    cudaGetSymbolAddress((void**)&hdi[1], g_hdi_b);
    cudaGetSymbolAddress((void**)&agg_mi, g_agg_mi);
    cudaGetSymbolAddress((void**)&agg_di, g_agg_di);
    cudaGetSymbolAddress((void**)&deg_mi, g_deg_mi);
    cudaGetSymbolAddress((void**)&deg_di, g_deg_di);

    cudaStream_t s = 0;

    // degrees (edge structure is an input; recompute every call)
    cudaMemsetAsync(deg_mi, 0, (size_t)NMI * sizeof(float), s);
    cudaMemsetAsync(deg_di, 0, (size_t)NDI * sizeof(float), s);
    deg_kernel<<<cdiv(E, 256), 256, 0, s>>>(edge_src, edge_dst, E, deg_mi, deg_di);

    // input projections: h = x @ W^T + b + emb
    gemm_dual<<<dim3(cdiv(NDI, BM), cdiv(128, BN)), 256, 0, s>>>(
        x_di, nullptr, W_di, nullptr, nullptr, b_di, emb_di, hdi[0],
        NDI, 128, 128, 0);
    gemm_dual<<<dim3(cdiv(NMI, BM), cdiv(128, BN)), 256, 0, s>>>(
        x_mi, nullptr, W_mi, nullptr, nullptr, b_mi, emb_mi, hmi[0],
        NMI, 256, 128, 0);

    const int cin[3]  = {128, 256, 128};
    const int cout[3] = {256, 128, 64};
    int cur = 0;
    for (int l = 0; l < 3; l++) {
        int K  = cin[l];
        int Co = cout[l];
        int relu = (l < 2) ? 1 : 0;

        cudaMemsetAsync(agg_mi, 0, (size_t)NMI * K * sizeof(float), s);
        cudaMemsetAsync(agg_di, 0, (size_t)NDI * K * sizeof(float), s);
        scatter_kernel<<<cdiv(E * 32, 256), 256, 0, s>>>(
            hmi[cur], hdi[cur], edge_src, edge_dst, E, K, agg_di, agg_mi);

        // new_di = (agg_di/deg_di) @ Wl_md^T + bl_md + h_di @ Wr_md^T
        gemm_dual<<<dim3(cdiv(NDI, BM), cdiv(Co, BN)), 256, 0, s>>>(
            agg_di, deg_di, Wl[l][0], hdi[cur], Wr[l][0], bl[l][0], nullptr,
            hdi[cur ^ 1], NDI, K, Co, relu);
        // new_mi = (agg_mi/deg_mi) @ Wl_dm^T + bl_dm + h_mi @ Wr_dm^T
        gemm_dual<<<dim3(cdiv(NMI, BM), cdiv(Co, BN)), 256, 0, s>>>(
            agg_mi, deg_mi, Wl[l][1], hmi[cur], Wr[l][1], bl[l][1], nullptr,
            hmi[cur ^ 1], NMI, K, Co, relu);

        cur ^= 1;
    }

    dot_kernel<<<cdiv(L * 16, 256), 256, 0, s>>>(
        hmi[cur], hdi[cur], label_src, label_dst, L, out);
}

// round 2
// speedup vs baseline: 1.3262x; 1.3262x over previous
#include <cuda_runtime.h>
#include <cstdint>

// ---------------------------------------------------------------------------
// Problem constants
// ---------------------------------------------------------------------------
#define NMI 100000
#define NDI 50000
#define HMAX 256

// ---------------------------------------------------------------------------
// Scratch: __device__ globals
// ---------------------------------------------------------------------------
__device__ float g_hmi_a[(size_t)NMI * HMAX];
__device__ float g_hmi_b[(size_t)NMI * HMAX];
__device__ float g_hdi_a[(size_t)NDI * HMAX];
__device__ float g_hdi_b[(size_t)NDI * HMAX];
__device__ float g_agg_mi[(size_t)NMI * HMAX];
__device__ float g_agg_di[(size_t)NDI * HMAX];
__device__ float g_deg_mi[NMI];
__device__ float g_deg_di[NDI];

static inline int cdiv(int a, int b) { return (a + b - 1) / b; }

// ---------------------------------------------------------------------------
// Degree count + inversion (store 1/max(deg,1) so GEMM just multiplies)
// ---------------------------------------------------------------------------
__global__ void deg_kernel(const int* __restrict__ src, const int* __restrict__ dst,
                           int E, float* __restrict__ deg_mi, float* __restrict__ deg_di)
{
    int i = blockIdx.x * blockDim.x + threadIdx.x;
    if (i < E) {
        atomicAdd(&deg_mi[src[i]], 1.0f);
        atomicAdd(&deg_di[dst[i]], 1.0f);
    }
}

__global__ void inv_kernel(float* __restrict__ deg, int n)
{
    int i = blockIdx.x * blockDim.x + threadIdx.x;
    if (i < n) deg[i] = 1.0f / fmaxf(deg[i], 1.0f);
}

// ---------------------------------------------------------------------------
// Vectorized global reduction
// ---------------------------------------------------------------------------
__device__ __forceinline__ void red_add_v4(float* p, float4 v)
{
    asm volatile("red.global.add.v4.f32 [%0], {%1, %2, %3, %4};"
                 :: "l"(p), "f"(v.x), "f"(v.y), "f"(v.z), "f"(v.w)
                 : "memory");
}

// ---------------------------------------------------------------------------
// Fused bidirectional scatter: one warp per edge.
// ---------------------------------------------------------------------------
__global__ void scatter_kernel(const float* __restrict__ hmi, const float* __restrict__ hdi,
                               const int* __restrict__ src, const int* __restrict__ dst,
                               int E, int C,
                               float* __restrict__ agg_di, float* __restrict__ agg_mi)
{
    int gw = (blockIdx.x * blockDim.x + threadIdx.x) >> 5;
    int lane = threadIdx.x & 31;
    if (gw >= E) return;
    int s = src[gw];
    int d = dst[gw];
    const float4* rs = (const float4*)(hmi + (size_t)s * C);
    const float4* rd = (const float4*)(hdi + (size_t)d * C);
    float*        ad = agg_di + (size_t)d * C;
    float*        am = agg_mi + (size_t)s * C;
    int n4 = C >> 2;
    for (int j = lane; j < n4; j += 32) {
        float4 a = rs[j];
        float4 b = rd[j];
        red_add_v4(ad + j * 4, a);
        red_add_v4(am + j * 4, b);
    }
}

// ---------------------------------------------------------------------------
// 3xTF32 tensor-core GEMM (split-precision: fp32-level accuracy on tf32 MMA)
//   D[n,c] = sum_k s(n)*A1[n,k]*W1[c,k] (+ sum_k A2[n,k]*W2[c,k])
//            + bias[c] (+ addend[n,c]) ; optional relu
// s(n) = invdeg[n] when invdeg != nullptr.
// CTA: 128 threads (4 warps, 2x2), tile 128x128, warp tile 64x64, BK=16.
// ---------------------------------------------------------------------------
#define BM 128
#define BN 128
#define BK 16
#define KPAD 4           // smem row stride = BK + KPAD = 20 uints (bank-safe)

__device__ __forceinline__ unsigned f2tf32(float f)
{
    unsigned u;
    asm("cvt.rna.tf32.f32 %0, %1;" : "=r"(u) : "f"(f));
    return u;
}

__device__ __forceinline__ void mma_tf32(float* d, const unsigned* a, unsigned b0, unsigned b1)
{
    asm volatile(
        "mma.sync.aligned.m16n8k8.row.col.f32.tf32.tf32.f32 "
        "{%0,%1,%2,%3}, {%4,%5,%6,%7}, {%8,%9}, {%0,%1,%2,%3};"
        : "+f"(d[0]), "+f"(d[1]), "+f"(d[2]), "+f"(d[3])
        : "r"(a[0]), "r"(a[1]), "r"(a[2]), "r"(a[3]), "r"(b0), "r"(b1));
}

__global__ __launch_bounds__(128)
void gemm_3xtf32(const float* __restrict__ A1, const float* __restrict__ invdeg,
                 const float* __restrict__ W1,
                 const float* __restrict__ A2, const float* __restrict__ W2,
                 const float* __restrict__ bias, const float* __restrict__ addend,
                 float* __restrict__ D, int N, int K, int Co, int relu)
{
    __shared__ unsigned As_h[BM][BK + KPAD];
    __shared__ unsigned As_l[BM][BK + KPAD];
    __shared__ unsigned Bs_h[BN][BK + KPAD];
    __shared__ unsigned Bs_l[BN][BK + KPAD];

    const int tid  = threadIdx.x;
    const int lane = tid & 31;
    const int wid  = tid >> 5;
    const int wm   = (wid & 1) * 64;
    const int wn   = (wid >> 1) * 64;
    const int gid  = lane >> 2;   // 0..7
    const int tig  = lane & 3;    // 0..3

    const int row0 = blockIdx.x * BM;
    const int col0 = blockIdx.y * BN;

    const int lrow = tid >> 2;    // 0..31 (row within 32-row pass)
    const int lc4  = tid & 3;     // float4 column group 0..3

    float acc[4][8][4];
#pragma unroll
    for (int i = 0; i < 4; i++)
#pragma unroll
        for (int j = 0; j < 8; j++)
#pragma unroll
            for (int q = 0; q < 4; q++) acc[i][j][q] = 0.0f;

    const int KT = (A2 != nullptr) ? 2 * K : K;

    float4 pa[4], pb[4];

    // ---- prefetch helper (inlined twice via lambda) ----
    auto load_tile = [&](int kt) {
        const int kg = kt + lc4 * 4;
        const bool first = (kg < K);
        const int  kk    = first ? kg : (kg - K);
#pragma unroll
        for (int p = 0; p < 4; p++) {
            int r  = lrow + p * 32;
            int ar = row0 + r;
            float4 v = make_float4(0.f, 0.f, 0.f, 0.f);
            if (ar < N) {
                if (first) {
                    v = *(const float4*)(A1 + (size_t)ar * K + kk);
                    if (invdeg) {
                        float s = invdeg[ar];
                        v.x *= s; v.y *= s; v.z *= s; v.w *= s;
                    }
                } else {
                    v = *(const float4*)(A2 + (size_t)ar * K + kk);
                }
            }
            pa[p] = v;
            int c = col0 + r;
            float4 w = make_float4(0.f, 0.f, 0.f, 0.f);
            if (c < Co) {
                const float* W = first ? W1 : W2;
                w = *(const float4*)(W + (size_t)c * K + kk);
            }
            pb[p] = w;
        }
    };

    auto store_tile = [&]() {
#pragma unroll
        for (int p = 0; p < 4; p++) {
            int r = lrow + p * 32;
            float4 v = pa[p];
            unsigned h0 = f2tf32(v.x), h1 = f2tf32(v.y), h2 = f2tf32(v.z), h3 = f2tf32(v.w);
            unsigned l0 = f2tf32(v.x - __uint_as_float(h0));
            unsigned l1 = f2tf32(v.y - __uint_as_float(h1));
            unsigned l2 = f2tf32(v.z - __uint_as_float(h2));
            unsigned l3 = f2tf32(v.w - __uint_as_float(h3));
            *(uint4*)&As_h[r][lc4 * 4] = make_uint4(h0, h1, h2, h3);
            *(uint4*)&As_l[r][lc4 * 4] = make_uint4(l0, l1, l2, l3);
            float4 w = pb[p];
            h0 = f2tf32(w.x); h1 = f2tf32(w.y); h2 = f2tf32(w.z); h3 = f2tf32(w.w);
            l0 = f2tf32(w.x - __uint_as_float(h0));
            l1 = f2tf32(w.y - __uint_as_float(h1));
            l2 = f2tf32(w.z - __uint_as_float(h2));
            l3 = f2tf32(w.w - __uint_as_float(h3));
            *(uint4*)&Bs_h[r][lc4 * 4] = make_uint4(h0, h1, h2, h3);
            *(uint4*)&Bs_l[r][lc4 * 4] = make_uint4(l0, l1, l2, l3);
        }
    };

    load_tile(0);

    for (int kt = 0; kt < KT; kt += BK) {
        store_tile();
        __syncthreads();
        if (kt + BK < KT) load_tile(kt + BK);

#pragma unroll
        for (int k8 = 0; k8 < 2; k8++) {
            const int kb = k8 * 8;
            unsigned ah[4][4], al[4][4];
#pragma unroll
            for (int mi = 0; mi < 4; mi++) {
                int r = wm + mi * 16 + gid;
                ah[mi][0] = As_h[r][kb + tig];
                ah[mi][1] = As_h[r + 8][kb + tig];
                ah[mi][2] = As_h[r][kb + tig + 4];
                ah[mi][3] = As_h[r + 8][kb + tig + 4];
                al[mi][0] = As_l[r][kb + tig];
                al[mi][1] = As_l[r + 8][kb + tig];
                al[mi][2] = As_l[r][kb + tig + 4];
                al[mi][3] = As_l[r + 8][kb + tig + 4];
            }
#pragma unroll
            for (int ni = 0; ni < 8; ni++) {
                int c = wn + ni * 8 + gid;
                unsigned bh0 = Bs_h[c][kb + tig];
                unsigned bh1 = Bs_h[c][kb + tig + 4];
                unsigned bl0 = Bs_l[c][kb + tig];
                unsigned bl1 = Bs_l[c][kb + tig + 4];
#pragma unroll
                for (int mi = 0; mi < 4; mi++) {
                    mma_tf32(acc[mi][ni], al[mi], bh0, bh1);   // lo*hi
                    mma_tf32(acc[mi][ni], ah[mi], bl0, bl1);   // hi*lo
                    mma_tf32(acc[mi][ni], ah[mi], bh0, bh1);   // hi*hi
                }
            }
        }
        __syncthreads();
    }

    // ---- epilogue ----
#pragma unroll
    for (int mi = 0; mi < 4; mi++) {
#pragma unroll
        for (int ni = 0; ni < 8; ni++) {
            int col = col0 + wn + ni * 8 + 2 * tig;
            if (col >= Co) continue;
            float b0 = bias ? bias[col]     : 0.0f;
            float b1 = bias ? bias[col + 1] : 0.0f;
#pragma unroll
            for (int half = 0; half < 2; half++) {
                int row = row0 + wm + mi * 16 + gid + half * 8;
                if (row >= N) continue;
                float v0 = acc[mi][ni][half * 2 + 0] + b0;
                float v1 = acc[mi][ni][half * 2 + 1] + b1;
                if (addend) {
                    float2 ad = *(const float2*)(addend + (size_t)row * Co + col);
                    v0 += ad.x; v1 += ad.y;
                }
                if (relu) { v0 = fmaxf(v0, 0.0f); v1 = fmaxf(v1, 0.0f); }
                *(float2*)(D + (size_t)row * Co + col) = make_float2(v0, v1);
            }
        }
    }
}

// ---------------------------------------------------------------------------
// Classifier dot product
// ---------------------------------------------------------------------------
__global__ void dot_kernel(const float* __restrict__ hmi, const float* __restrict__ hdi,
                           const int* __restrict__ lsrc, const int* __restrict__ ldst,
                           int L, float* __restrict__ out)
{
    int idx = blockIdx.x * blockDim.x + threadIdx.x;
    int lab = idx >> 4;
    int ln  = idx & 15;
    if (lab >= L) return;
    int s = lsrc[lab];
    int d = ldst[lab];
    float4 a = *(const float4*)(hmi + (size_t)s * 64 + ln * 4);
    float4 b = *(const float4*)(hdi + (size_t)d * 64 + ln * 4);
    float v = a.x * b.x + a.y * b.y + a.z * b.z + a.w * b.w;
    v += __shfl_down_sync(0xFFFFFFFFu, v, 8, 16);
    v += __shfl_down_sync(0xFFFFFFFFu, v, 4, 16);
    v += __shfl_down_sync(0xFFFFFFFFu, v, 2, 16);
    v += __shfl_down_sync(0xFFFFFFFFu, v, 1, 16);
    if (ln == 0) out[lab] = v;
}

// ---------------------------------------------------------------------------
// Launch
// ---------------------------------------------------------------------------
extern "C" void kernel_launch(void* const* d_in, const int* in_sizes, int n_in,
                              void* d_out, int out_size)
{
    const float* x_mi   = (const float*)d_in[0];
    const float* x_di   = (const float*)d_in[1];
    const float* W_mi   = (const float*)d_in[2];
    const float* b_mi   = (const float*)d_in[3];
    const float* W_di   = (const float*)d_in[4];
    const float* b_di   = (const float*)d_in[5];
    const float* emb_mi = (const float*)d_in[6];
    const float* emb_di = (const float*)d_in[7];

    const float *Wl[3][2], *bl[3][2], *Wr[3][2];  // [layer][0=md,1=dm]
    int idx = 8;
    for (int l = 0; l < 3; l++)
        for (int r = 0; r < 2; r++) {
            Wl[l][r] = (const float*)d_in[idx++];
            bl[l][r] = (const float*)d_in[idx++];
            Wr[l][r] = (const float*)d_in[idx++];
        }
    const int* edge_src  = (const int*)d_in[26];
    const int* edge_dst  = (const int*)d_in[27];
    const int* label_src = (const int*)d_in[28];
    const int* label_dst = (const int*)d_in[29];
    const int E = in_sizes[26];
    const int L = in_sizes[28];
    float* out = (float*)d_out;

    float *hmi[2], *hdi[2], *agg_mi, *agg_di, *deg_mi, *deg_di;
    cudaGetSymbolAddress((void**)&hmi[0], g_hmi_a);
    cudaGetSymbolAddress((void**)&hmi[1], g_hmi_b);
    cudaGetSymbolAddress((void**)&hdi[0], g_hdi_a);
    cudaGetSymbolAddress((void**)&hdi[1], g_hdi_b);
    cudaGetSymbolAddress((void**)&agg_mi, g_agg_mi);
    cudaGetSymbolAddress((void**)&agg_di, g_agg_di);
    cudaGetSymbolAddress((void**)&deg_mi, g_deg_mi);
    cudaGetSymbolAddress((void**)&deg_di, g_deg_di);

    cudaStream_t s = 0;

    // degrees -> inverse degrees
    cudaMemsetAsync(deg_mi, 0, (size_t)NMI * sizeof(float), s);
    cudaMemsetAsync(deg_di, 0, (size_t)NDI * sizeof(float), s);
    deg_kernel<<<cdiv(E, 256), 256, 0, s>>>(edge_src, edge_dst, E, deg_mi, deg_di);
    inv_kernel<<<cdiv(NMI, 256), 256, 0, s>>>(deg_mi, NMI);
    inv_kernel<<<cdiv(NDI, 256), 256, 0, s>>>(deg_di, NDI);

    // input projections: h = x @ W^T + b + emb
    gemm_3xtf32<<<dim3(cdiv(NDI, BM), 1), 128, 0, s>>>(
        x_di, nullptr, W_di, nullptr, nullptr, b_di, emb_di, hdi[0],
        NDI, 128, 128, 0);
    gemm_3xtf32<<<dim3(cdiv(NMI, BM), 1), 128, 0, s>>>(
        x_mi, nullptr, W_mi, nullptr, nullptr, b_mi, emb_mi, hmi[0],
        NMI, 256, 128, 0);

    const int cin[3]  = {128, 256, 128};
    const int cout[3] = {256, 128, 64};
    int cur = 0;
    for (int l = 0; l < 3; l++) {
        int K  = cin[l];
        int Co = cout[l];
        int relu = (l < 2) ? 1 : 0;

        cudaMemsetAsync(agg_mi, 0, (size_t)NMI * K * sizeof(float), s);
        cudaMemsetAsync(agg_di, 0, (size_t)NDI * K * sizeof(float), s);
        scatter_kernel<<<cdiv(E * 32, 256), 256, 0, s>>>(
            hmi[cur], hdi[cur], edge_src, edge_dst, E, K, agg_di, agg_mi);

        gemm_3xtf32<<<dim3(cdiv(NDI, BM), cdiv(Co, BN)), 128, 0, s>>>(
            agg_di, deg_di, Wl[l][0], hdi[cur], Wr[l][0], bl[l][0], nullptr,
            hdi[cur ^ 1], NDI, K, Co, relu);
        gemm_3xtf32<<<dim3(cdiv(NMI, BM), cdiv(Co, BN)), 128, 0, s>>>(
            agg_mi, deg_mi, Wl[l][1], hmi[cur], Wr[l][1], bl[l][1], nullptr,
            hmi[cur ^ 1], NMI, K, Co, relu);

        cur ^= 1;
    }

    dot_kernel<<<cdiv(L * 16, 256), 256, 0, s>>>(
        hmi[cur], hdi[cur], label_src, label_dst, L, out);
}